// round 3
// baseline (speedup 1.0000x reference)
#include <cuda_runtime.h>
#include <cuda_bf16.h>

#define M_LFS 20
#define ROWS_PER_THREAD 4
#define BLOCK 256
#define EPSF 1e-6f

__device__ double g_acc;

__global__ void init_acc_kernel() {
    g_acc = 0.0;
}

__global__ __launch_bounds__(BLOCK) void ratner_mle_kernel(
    const int* __restrict__ L,
    const float* __restrict__ alpha,
    const float* __restrict__ beta,
    int n_rows)
{
    // Lookup tables: tab_pos[j*3 + (l+1)] = factor for y=+1, label l in {-1,0,1}
    __shared__ float tab_pos[M_LFS * 3];
    __shared__ float tab_neg[M_LFS * 3];

    int tid = threadIdx.x;
    if (tid < M_LFS) {
        float a = 1.0f / (1.0f + expf(-alpha[tid]));
        float b = beta[tid];
        float abstain  = 1.0f - b;
        float agree    = b * a;
        float disagree = b * (1.0f - a);
        tab_pos[tid * 3 + 0] = disagree;  // l == -1
        tab_pos[tid * 3 + 1] = abstain;   // l ==  0
        tab_pos[tid * 3 + 2] = agree;     // l == +1
        tab_neg[tid * 3 + 0] = agree;
        tab_neg[tid * 3 + 1] = abstain;
        tab_neg[tid * 3 + 2] = disagree;
    }
    __syncthreads();

    long long gtid = (long long)blockIdx.x * BLOCK + tid;
    long long base = gtid * ROWS_PER_THREAD;

    float sum = 0.0f;

    if (base + ROWS_PER_THREAD <= n_rows) {
        // Fast path: all 4 rows in bounds. Front-batch all 20 LDG.128s for MLP.
        int4 v[ROWS_PER_THREAD][5];
        #pragma unroll
        for (int r = 0; r < ROWS_PER_THREAD; r++) {
            const int4* p = (const int4*)(L + (base + r) * M_LFS);
            #pragma unroll
            for (int q = 0; q < 5; q++) v[r][q] = p[q];
        }
        #pragma unroll
        for (int r = 0; r < ROWS_PER_THREAD; r++) {
            int lv[M_LFS];
            #pragma unroll
            for (int q = 0; q < 5; q++) {
                lv[q * 4 + 0] = v[r][q].x;
                lv[q * 4 + 1] = v[r][q].y;
                lv[q * 4 + 2] = v[r][q].z;
                lv[q * 4 + 3] = v[r][q].w;
            }
            float pp = 1.0f, pn = 1.0f;
            #pragma unroll
            for (int j = 0; j < M_LFS; j++) {
                int c = lv[j] + 1;           // {-1,0,1} -> {0,1,2}
                pp *= tab_pos[j * 3 + c];
                pn *= tab_neg[j * 3 + c];
            }
            sum += __logf(pp + pn + EPSF);
        }
    } else {
        // Tail path: per-row bounds check.
        for (int r = 0; r < ROWS_PER_THREAD; r++) {
            long long row = base + r;
            if (row < n_rows) {
                const int* p = L + row * M_LFS;
                float pp = 1.0f, pn = 1.0f;
                #pragma unroll
                for (int j = 0; j < M_LFS; j++) {
                    int c = p[j] + 1;
                    pp *= tab_pos[j * 3 + c];
                    pn *= tab_neg[j * 3 + c];
                }
                sum += __logf(pp + pn + EPSF);
            }
        }
    }

    // Warp reduce
    #pragma unroll
    for (int off = 16; off > 0; off >>= 1)
        sum += __shfl_xor_sync(0xFFFFFFFFu, sum, off);

    __shared__ float wsum[BLOCK / 32];
    int lane = tid & 31;
    int warp = tid >> 5;
    if (lane == 0) wsum[warp] = sum;
    __syncthreads();

    if (warp == 0) {
        float s = (lane < BLOCK / 32) ? wsum[lane] : 0.0f;
        #pragma unroll
        for (int off = 4; off > 0; off >>= 1)
            s += __shfl_xor_sync(0xFFFFFFFFu, s, off);
        if (lane == 0)
            atomicAdd(&g_acc, (double)s);
    }
}

__global__ void finalize_kernel(float* __restrict__ out, int out_size) {
    float v = (float)(-g_acc);
    for (int i = threadIdx.x; i < out_size; i += blockDim.x)
        out[i] = v;
}

extern "C" void kernel_launch(void* const* d_in, const int* in_sizes, int n_in,
                              void* d_out, int out_size) {
    const int*   L     = (const int*)d_in[0];
    const float* alpha = (const float*)d_in[1];
    const float* beta  = (const float*)d_in[2];
    float*       out   = (float*)d_out;

    int n_rows = in_sizes[0] / M_LFS;

    int rows_per_block = BLOCK * ROWS_PER_THREAD;
    int grid = (n_rows + rows_per_block - 1) / rows_per_block;

    init_acc_kernel<<<1, 1>>>();
    ratner_mle_kernel<<<grid, BLOCK>>>(L, alpha, beta, n_rows);
    finalize_kernel<<<1, 32>>>(out, out_size);
}